// round 7
// baseline (speedup 1.0000x reference)
#include <cuda_runtime.h>
#include <cuda_fp16.h>

// PassiveWaveDigitalMixer — fused 9-point periodic stencil + gated flows.
// B=4, C=128, H=W=256, O=16, M=32 (fixed shapes).
// R6: R5 math (packed-half2 gating, fp32 flows), but steer multipliers live
// in SHARED (3x LDS.128 per row) instead of 48 registers, and row loads are
// staged (8 front-batched + 2 issued after the first vsum) to cut peak
// register liveness. __launch_bounds__(256,3) -> <=85 regs -> 24 warps/SM.

constexpr int B = 4, C = 128, H = 256, W = 256, O = 16, M = 32;
constexpr int HW = H * W;
constexpr float GAIN_CAP = 0.99f;
constexpr float EPS = 1e-4f;

__device__ __forceinline__ float softplus_eps(float p) {
    return fmaxf(p, 0.0f) + log1pf(expf(-fabsf(p))) + EPS;
}

__device__ __forceinline__ float4 add4(float4 a, float4 b) {
    return make_float4(a.x + b.x, a.y + b.y, a.z + b.z, a.w + b.w);
}

__device__ __forceinline__ __half2 u2h(unsigned u) {
    __half2 r;
    *reinterpret_cast<unsigned*>(&r) = u;
    return r;
}

__global__ __launch_bounds__(256, 3)
void pwdm_kernel(const float* __restrict__ x,
                 const float* __restrict__ steer,
                 const float* __restrict__ modulation,
                 const float* __restrict__ r_center,
                 const float* __restrict__ r_horizontal,
                 const float* __restrict__ r_vertical,
                 const float* __restrict__ r_diag,
                 const float* __restrict__ gain_h,
                 const float* __restrict__ gain_v,
                 const float* __restrict__ gain_d,
                 const float* __restrict__ steer_w,
                 const float* __restrict__ mod_w,
                 float* __restrict__ out)
{
    __shared__ float s_invh[C], s_invv[C], s_invd[C];
    __shared__ float s_gh[C],   s_gv[C],   s_gd[C];
    __shared__ __half s_t[4][3][W];   // pre-expanded (1 + 0.2*tanh(field))

    const int tx  = threadIdx.x;          // 0..31 lane (8 w-elems each)
    const int ty  = threadIdx.y;          // 0..7  channel sub-lane
    const int tid = ty * 32 + tx;
    const int h0  = blockIdx.x * 4;       // first of the 4-row group
    const int b   = blockIdx.y;

    // --- modulation deltas (broadcast loads, every thread) ---
    float d0 = 0.f, d1 = 0.f, d2 = 0.f;
    #pragma unroll
    for (int m = 0; m < M; m++) {
        float mv = modulation[b * M + m];
        d0 = fmaf(mv, mod_w[0 * M + m], d0);
        d1 = fmaf(mv, mod_w[1 * M + m], d1);
        d2 = fmaf(mv, mod_w[2 * M + m], d2);
    }
    d0 = tanhf(d0); d1 = tanhf(d1); d2 = tanhf(d2);

    // --- per-channel constants ---
    if (tid < C) {
        float spc = softplus_eps(r_center[tid]);
        s_invh[tid] = 1.0f / (spc + softplus_eps(r_horizontal[tid]));
        s_invv[tid] = 1.0f / (spc + softplus_eps(r_vertical[tid]));
        s_invd[tid] = 1.0f / (2.0f * (spc + softplus_eps(r_diag[tid])));
        s_gh[tid] = tanhf(gain_h[tid]) * (1.0f + 0.1f * d0);
        s_gv[tid] = tanhf(gain_v[tid]) * (1.0f + 0.1f * d1);
        s_gd[tid] = tanhf(gain_d[tid]) * (1.0f + 0.1f * d2);
    }

    // --- steer-field multipliers for 4 rows; thread tid covers w = tid ---
    #pragma unroll
    for (int r = 0; r < 4; r++) {
        float a0 = 0.f, a1 = 0.f, a2 = 0.f;
        const float* sp = steer + ((size_t)b * O * H + (h0 + r)) * W + tid;
        #pragma unroll
        for (int o = 0; o < O; o++) {
            float v = sp[(size_t)o * HW];
            a0 = fmaf(v, steer_w[0 * O + o], a0);
            a1 = fmaf(v, steer_w[1 * O + o], a1);
            a2 = fmaf(v, steer_w[2 * O + o], a2);
        }
        s_t[r][0][tid] = __float2half(fmaf(0.2f, tanhf(a0), 1.0f));
        s_t[r][1][tid] = __float2half(fmaf(0.2f, tanhf(a1), 1.0f));
        s_t[r][2][tid] = __float2half(fmaf(0.2f, tanhf(a2), 1.0f));
    }
    __syncthreads();

    const int w0 = tx * 8;
    const int hm = (h0 - 1) & (H - 1);
    const int hp = (h0 + 4) & (H - 1);
    const size_t base = (size_t)b * C * HW + (size_t)ty * HW + w0;
    const float* pm = x + base + (size_t)hm * W;
    const float* p0 = x + base + (size_t)h0 * W;
    const float* pp = x + base + (size_t)hp * W;
    float*       o0 = out + base + (size_t)h0 * W;
    const size_t cstep = (size_t)8 * HW;

    const unsigned FULL = 0xffffffffu;
    const int laneL = (tx + 31) & 31;
    const int laneR = (tx + 1) & 31;
    const __half2 zero2 = __float2half2_rn(0.0f);
    const __half2 cap2  = __float2half2_rn(GAIN_CAP);

    float invh, invv, invd;
    __half2 gh2, gv2, gd2;

    // one output row: centers (cA,cB), vertical sums (sA,sB); steer mults
    // come from shared via 3x LDS.128.
    auto do_row = [&](float4 cA_, float4 cB_, float4 sA_, float4 sB_,
                      int r, float* op) {
        uint4 uH = *reinterpret_cast<const uint4*>(&s_t[r][0][w0]);
        uint4 uV = *reinterpret_cast<const uint4*>(&s_t[r][1][w0]);
        uint4 uD = *reinterpret_cast<const uint4*>(&s_t[r][2][w0]);
        unsigned mh[4] = {uH.x, uH.y, uH.z, uH.w};
        unsigned mv[4] = {uV.x, uV.y, uV.z, uV.w};
        unsigned md[4] = {uD.x, uD.y, uD.z, uD.w};

        float ce[10], se[10];
        ce[1] = cA_.x; ce[2] = cA_.y; ce[3] = cA_.z; ce[4] = cA_.w;
        ce[5] = cB_.x; ce[6] = cB_.y; ce[7] = cB_.z; ce[8] = cB_.w;
        se[1] = sA_.x; se[2] = sA_.y; se[3] = sA_.z; se[4] = sA_.w;
        se[5] = sB_.x; se[6] = sB_.y; se[7] = sB_.z; se[8] = sB_.w;
        ce[0] = __shfl_sync(FULL, ce[8], laneL);
        ce[9] = __shfl_sync(FULL, ce[1], laneR);
        se[0] = __shfl_sync(FULL, se[8], laneL);
        se[9] = __shfl_sync(FULL, se[1], laneR);

        float r8[8];
        #pragma unroll
        for (int j = 0; j < 4; j++) {
            __half2 gH = __hmin2(__hmax2(__hmul2(gh2, u2h(mh[j])), zero2), cap2);
            __half2 gV = __hmin2(__hmax2(__hmul2(gv2, u2h(mv[j])), zero2), cap2);
            __half2 gD = __hmin2(__hmax2(__hmul2(gd2, u2h(md[j])), zero2), cap2);
            float2 ghf = __half22float2(gH);
            float2 gvf = __half22float2(gV);
            float2 gdf = __half22float2(gD);
            #pragma unroll
            for (int k = 0; k < 2; k++) {
                const int i = 2 * j + k;
                float cv = ce[i + 1];
                float fh = (ce[i] + ce[i + 2] - 2.0f * cv) * invh;
                float fv = (se[i + 1]          - 2.0f * cv) * invv;
                float fd = (se[i] + se[i + 2]  - 4.0f * cv) * invd;
                float gh = k ? ghf.y : ghf.x;
                float gv = k ? gvf.y : gvf.x;
                float gd = k ? gdf.y : gdf.x;
                r8[i] = fmaf(gh, fh, fmaf(gv, fv, fmaf(gd, fd, cv)));
            }
        }
        *reinterpret_cast<float4*>(op)     = make_float4(r8[0], r8[1], r8[2], r8[3]);
        *reinterpret_cast<float4*>(op + 4) = make_float4(r8[4], r8[5], r8[6], r8[7]);
    };

    for (int c = ty; c < C; c += 8) {
        // front-batch 8 row-vector loads (rows m, a, b, c)
        float4 mA = *reinterpret_cast<const float4*>(pm);
        float4 mB = *reinterpret_cast<const float4*>(pm + 4);
        float4 aA = *reinterpret_cast<const float4*>(p0);
        float4 aB = *reinterpret_cast<const float4*>(p0 + 4);
        float4 bA = *reinterpret_cast<const float4*>(p0 + W);
        float4 bB = *reinterpret_cast<const float4*>(p0 + W + 4);
        float4 cA = *reinterpret_cast<const float4*>(p0 + 2 * W);
        float4 cB = *reinterpret_cast<const float4*>(p0 + 2 * W + 4);

        invh = s_invh[c]; invv = s_invv[c]; invd = s_invd[c];
        gh2 = __float2half2_rn(s_gh[c]);
        gv2 = __float2half2_rn(s_gv[c]);
        gd2 = __float2half2_rn(s_gd[c]);

        // vsum for row h0 first: m dies here, then issue rows d and p
        float4 v0A = add4(mA, bA), v0B = add4(mB, bB);
        float4 dA = *reinterpret_cast<const float4*>(p0 + 3 * W);
        float4 dB = *reinterpret_cast<const float4*>(p0 + 3 * W + 4);
        float4 pA = *reinterpret_cast<const float4*>(pp);
        float4 pB = *reinterpret_cast<const float4*>(pp + 4);

        // row h0: vsum = m + b
        do_row(aA, aB, v0A, v0B, 0, o0);
        // row h1: vsum = a + c (a dies)
        do_row(bA, bB, add4(aA, cA), add4(aB, cB), 1, o0 + W);
        // row h2: vsum = b + d (b dies)
        do_row(cA, cB, add4(bA, dA), add4(bB, dB), 2, o0 + 2 * W);
        // row h3: vsum = c + p
        do_row(dA, dB, add4(cA, pA), add4(cB, pB), 3, o0 + 3 * W);

        pm += cstep; p0 += cstep; pp += cstep; o0 += cstep;
    }
}

extern "C" void kernel_launch(void* const* d_in, const int* in_sizes, int n_in,
                              void* d_out, int out_size)
{
    const float* x            = (const float*)d_in[0];
    const float* steer        = (const float*)d_in[1];
    const float* modulation   = (const float*)d_in[2];
    const float* r_center     = (const float*)d_in[3];
    const float* r_horizontal = (const float*)d_in[4];
    const float* r_vertical   = (const float*)d_in[5];
    const float* r_diag       = (const float*)d_in[6];
    const float* gain_h       = (const float*)d_in[7];
    const float* gain_v       = (const float*)d_in[8];
    const float* gain_d       = (const float*)d_in[9];
    const float* steer_w      = (const float*)d_in[10];
    const float* mod_w        = (const float*)d_in[11];
    float* out = (float*)d_out;

    dim3 block(32, 8, 1);       // one warp per full W row-quad, 8 channel lanes
    dim3 grid(H / 4, B, 1);     // one block per (4-row group, b)
    pwdm_kernel<<<grid, block>>>(x, steer, modulation,
                                 r_center, r_horizontal, r_vertical, r_diag,
                                 gain_h, gain_v, gain_d,
                                 steer_w, mod_w, out);
}